// round 12
// baseline (speedup 1.0000x reference)
#include <cuda_runtime.h>
#include <math.h>

#define BATCH 8192
#define W 256
#define KCHUNK 128
#define NKCH  (BATCH / KCHUNK)       // 64
#define NPAIR 10
#define NCB   64
#define ROWS_PER_CB (BATCH / NCB)    // 128

// Device scratch (no allocations allowed).
__device__ float g_G[W * W];          // Gram accumulator
__device__ float g_colsum[NCB][W];    // partial column sums
__device__ float g_mu[W];             // column means
__device__ float g_sumsq;             // scalar accumulator for ||D||^2
__device__ int   g_fin_count = 0;     // finalize completion counter (self-resetting)

// Upper-triangular 64x64 tile-pair enumeration: (ti, tj) with ti <= tj.
__constant__ int c_ti[NPAIR] = {0,0,0,0,1,1,1,2,2,3};
__constant__ int c_tj[NPAIR] = {0,1,2,3,1,2,3,2,3,3};

// ---- f32x2 packed-FMA helpers --------------------------------------------
__device__ __forceinline__ unsigned long long pack_f32(float lo, float hi) {
    unsigned long long r;
    asm("mov.b64 %0, {%1, %2};" : "=l"(r) : "f"(lo), "f"(hi));
    return r;
}
__device__ __forceinline__ void fma2(unsigned long long &acc,
                                     unsigned long long a, unsigned long long b) {
    asm("fma.rn.f32x2 %0, %1, %2, %0;" : "+l"(acc) : "l"(a), "l"(b));
}
__device__ __forceinline__ float2 unpack_f32x2(unsigned long long v) {
    float lo, hi;
    asm("mov.b64 {%0, %1}, %2;" : "=f"(lo), "=f"(hi) : "l"(v));
    return make_float2(lo, hi);
}

// ---------------------------------------------------------------------------
// K1: partial column sums + zero G + zero sumsq. 64 blocks x 256 threads.
// ---------------------------------------------------------------------------
__global__ void colsum_kernel(const float* __restrict__ E) {
    const int t = threadIdx.x;
    const int b = blockIdx.x;
    const int gid = b * 256 + t;

    // Zero the Gram accumulator (graph replays; must re-zero every launch).
    ((float4*)g_G)[gid] = make_float4(0.f, 0.f, 0.f, 0.f);
    if (gid == 0) g_sumsq = 0.0f;

    // Column partial sums, coalesced, 4 independent accumulators for MLP.
    const float* p = E + (size_t)b * ROWS_PER_CB * W + t;
    float s0 = 0.f, s1 = 0.f, s2 = 0.f, s3 = 0.f;
    #pragma unroll 8
    for (int r = 0; r < ROWS_PER_CB; r += 4) {
        s0 += p[(size_t)(r + 0) * W];
        s1 += p[(size_t)(r + 1) * W];
        s2 += p[(size_t)(r + 2) * W];
        s3 += p[(size_t)(r + 3) * W];
    }
    g_colsum[b][t] = (s0 + s1) + (s2 + s3);
}

// ---------------------------------------------------------------------------
// K2: Gram, symmetric tiles, diagonal-pair FFMA2. 641 blocks x 128 threads.
// Block bid < 640: pair = bid/64, chunk = bid%64, 64x64 tile, 8x4 micro-tile.
// Block bid == 640: computes g_mu from g_colsum (off the critical path).
// ---------------------------------------------------------------------------
__global__ void gram_kernel(const float* __restrict__ E) {
    const int bid = blockIdx.x;
    const int tid = threadIdx.x;

    if (bid == NPAIR * NKCH) {
        // mu block: 128 threads, 2 columns each.
        #pragma unroll
        for (int h = 0; h < 2; ++h) {
            int c = tid + h * 128;
            float s = 0.0f;
            #pragma unroll 8
            for (int b = 0; b < NCB; ++b) s += g_colsum[b][c];
            g_mu[c] = s * (1.0f / BATCH);
        }
        return;
    }

    __shared__ float As[32][64];
    __shared__ float Bs[32][64];

    const int pair  = bid / NKCH;
    const int chunk = bid % NKCH;
    const int tx  = tid & 7;          // 8 i-groups of 8 rows
    const int ty  = tid >> 3;         // 16 j-groups of 4 cols
    const int i0  = c_ti[pair] * 64;
    const int j0  = c_tj[pair] * 64;
    const int k0  = chunk * KCHUNK;

    // accA[p][q] = {G[ib+2p, jb+2q],   G[ib+2p+1, jb+2q+1]}
    // accB[p][q] = {G[ib+2p, jb+2q+1], G[ib+2p+1, jb+2q]}
    unsigned long long accA[4][2], accB[4][2];
    #pragma unroll
    for (int p = 0; p < 4; ++p)
        #pragma unroll
        for (int q = 0; q < 2; ++q) { accA[p][q] = 0ull; accB[p][q] = 0ull; }

    for (int kc = 0; kc < KCHUNK; kc += 32) {
        // Stage 32 rows x 64 cols of both operand column blocks.
        #pragma unroll
        for (int qq = 0; qq < 4; ++qq) {
            int idx = qq * 128 + tid;     // 0..511
            int row = idx >> 4;
            int f   = idx & 15;
            size_t base = (size_t)(k0 + kc + row) * W;
            ((float4*)As[row])[f] = ((const float4*)(E + base + i0))[f];
            ((float4*)Bs[row])[f] = ((const float4*)(E + base + j0))[f];
        }
        __syncthreads();

        #pragma unroll
        for (int kk = 0; kk < 32; ++kk) {
            // a: 8 floats as 2x ulonglong2 -> 4 ready-made f32x2 pairs (no MOVs)
            ulonglong2 A0 = *(const ulonglong2*)&As[kk][tx * 8];
            ulonglong2 A1 = *(const ulonglong2*)&As[kk][tx * 8 + 4];
            float4 b = *(const float4*)&Bs[kk][ty * 4];
            unsigned long long b01 = pack_f32(b.x, b.y);   // reg-coalesced
            unsigned long long b10 = pack_f32(b.y, b.x);   // swapped (2 MOV)
            unsigned long long b23 = pack_f32(b.z, b.w);
            unsigned long long b32 = pack_f32(b.w, b.z);

            fma2(accA[0][0], A0.x, b01);  fma2(accB[0][0], A0.x, b10);
            fma2(accA[0][1], A0.x, b23);  fma2(accB[0][1], A0.x, b32);
            fma2(accA[1][0], A0.y, b01);  fma2(accB[1][0], A0.y, b10);
            fma2(accA[1][1], A0.y, b23);  fma2(accB[1][1], A0.y, b32);
            fma2(accA[2][0], A1.x, b01);  fma2(accB[2][0], A1.x, b10);
            fma2(accA[2][1], A1.x, b23);  fma2(accB[2][1], A1.x, b32);
            fma2(accA[3][0], A1.y, b01);  fma2(accB[3][0], A1.y, b10);
            fma2(accA[3][1], A1.y, b23);  fma2(accB[3][1], A1.y, b32);
        }
        __syncthreads();
    }

    const int ib = i0 + tx * 8;
    const int jb = j0 + ty * 4;
    #pragma unroll
    for (int p = 0; p < 4; ++p) {
        #pragma unroll
        for (int q = 0; q < 2; ++q) {
            float2 va = unpack_f32x2(accA[p][q]);
            float2 vb = unpack_f32x2(accB[p][q]);
            int gi = ib + 2 * p;
            int gj = jb + 2 * q;
            atomicAdd(&g_G[gi * W + gj],           va.x);
            atomicAdd(&g_G[gi * W + gj + 1],       vb.x);
            atomicAdd(&g_G[(gi + 1) * W + gj],     vb.y);
            atomicAdd(&g_G[(gi + 1) * W + gj + 1], va.y);
        }
    }
}

// ---------------------------------------------------------------------------
// K3: finalize. 128 blocks x 256 threads; block b -> rows b and 255-b.
// Last block to finish computes sqrt and writes the output scalar.
// ---------------------------------------------------------------------------
__global__ void finalize_kernel(float* __restrict__ out) {
    __shared__ float mu[W];
    __shared__ float red[256];

    const int t = threadIdx.x;
    mu[t] = g_mu[t];
    __syncthreads();

    const float invB = 1.0f / BATCH;
    float acc = 0.0f;
    int rows[2] = {(int)blockIdx.x, (W - 1) - (int)blockIdx.x};
    #pragma unroll
    for (int r = 0; r < 2; ++r) {
        int i = rows[r];
        int j = i + t;                 // upper triangle only
        if (j < W) {
            float d = g_G[i * W + j] * invB - mu[i] * mu[j] - (j == i ? 1.0f : 0.0f);
            acc += (j == i ? 1.0f : 2.0f) * d * d;
        }
    }

    red[t] = acc;
    __syncthreads();
    #pragma unroll
    for (int st = 128; st > 0; st >>= 1) {
        if (t < st) red[t] += red[t + st];
        __syncthreads();
    }

    if (t == 0) {
        atomicAdd(&g_sumsq, red[0]);
        __threadfence();
        int c = atomicAdd(&g_fin_count, 1);
        if (c == 127) {
            float total = atomicAdd(&g_sumsq, 0.0f);  // coherent read
            out[0] = sqrtf(total);
            g_fin_count = 0;                          // reset for next replay
        }
    }
}

// ---------------------------------------------------------------------------
extern "C" void kernel_launch(void* const* d_in, const int* in_sizes, int n_in,
                              void* d_out, int out_size) {
    const float* E = (const float*)d_in[0];   // [8192, 256] fp32
    float* out = (float*)d_out;

    colsum_kernel<<<NCB, 256>>>(E);
    gram_kernel<<<NPAIR * NKCH + 1, 128>>>(E);
    finalize_kernel<<<W / 2, 256>>>(out);
}

// round 13
// speedup vs baseline: 1.4772x; 1.4772x over previous
#include <cuda_runtime.h>
#include <math.h>

#define BATCH 8192
#define W 256
#define NKCH 32
#define KCHUNK (BATCH / NKCH)        // 256
#define NPAIR 10
#define NCSB 512                     // colsum blocks
#define ROWS_PER_CSB (BATCH / NCSB)  // 16

// Device scratch (no allocations allowed).
__device__ float g_Gs[NKCH][W * W];   // per-K-chunk Gram partials (8 MB)
__device__ float g_musum[W] = {};     // column sums  (self-resetting)
__device__ float g_sqsum[W] = {};     // column sum-of-squares (self-resetting)
__device__ float g_sumsq;             // ||D||^2 accumulator
__device__ int   g_fin_count = 0;     // finalize completion counter (self-resetting)

// Upper-triangular 64x64 tile-pair enumeration: (ti, tj) with ti <= tj.
__constant__ int c_ti[NPAIR] = {0,0,0,0,1,1,1,2,2,3};
__constant__ int c_tj[NPAIR] = {0,1,2,3,1,2,3,2,3,3};

// ---- helpers ---------------------------------------------------------------
__device__ __forceinline__ unsigned f2tf32(float x) {
    unsigned r;
    asm("cvt.rna.tf32.f32 %0, %1;" : "=r"(r) : "f"(x));
    return r;
}
__device__ __forceinline__ void mma_tf32(float* d, const unsigned* a, const unsigned* b) {
    asm("mma.sync.aligned.m16n8k8.row.col.f32.tf32.tf32.f32 "
        "{%0,%1,%2,%3}, {%4,%5,%6,%7}, {%8,%9}, {%0,%1,%2,%3};"
        : "+f"(d[0]), "+f"(d[1]), "+f"(d[2]), "+f"(d[3])
        : "r"(a[0]), "r"(a[1]), "r"(a[2]), "r"(a[3]), "r"(b[0]), "r"(b[1]));
}

// ---------------------------------------------------------------------------
// K1: column sums + sum-of-squares (exact fp32 diagonal). 512 blocks x 256 thr.
// Block b handles 16 rows; thread t owns column t. Spread atomics into
// g_musum/g_sqsum (zeroed at load time and self-reset by finalize).
// ---------------------------------------------------------------------------
__global__ void colsum_kernel(const float* __restrict__ E) {
    const int t = threadIdx.x;
    const int b = blockIdx.x;
    if (b == 0 && t == 0) g_sumsq = 0.0f;

    const float* p = E + (size_t)b * ROWS_PER_CSB * W + t;
    float s0 = 0.f, s1 = 0.f, s2 = 0.f, s3 = 0.f;
    float q0 = 0.f, q1 = 0.f, q2 = 0.f, q3 = 0.f;
    #pragma unroll
    for (int r = 0; r < ROWS_PER_CSB; r += 4) {
        float x0 = p[(size_t)(r + 0) * W];
        float x1 = p[(size_t)(r + 1) * W];
        float x2 = p[(size_t)(r + 2) * W];
        float x3 = p[(size_t)(r + 3) * W];
        s0 += x0; q0 = fmaf(x0, x0, q0);
        s1 += x1; q1 = fmaf(x1, x1, q1);
        s2 += x2; q2 = fmaf(x2, x2, q2);
        s3 += x3; q3 = fmaf(x3, x3, q3);
    }
    atomicAdd(&g_musum[t], (s0 + s1) + (s2 + s3));
    atomicAdd(&g_sqsum[t], (q0 + q1) + (q2 + q3));
}

// ---------------------------------------------------------------------------
// K2: Gram via TF32 tensor-core MMA, symmetric 64x64 tile-pairs.
// Grid 320 = 10 pairs x 32 K-chunks; 256 threads = 8 warps, warp tile 16x32.
// Partials stored (no atomics) to g_Gs[chunk].
// ---------------------------------------------------------------------------
__global__ __launch_bounds__(256) void gram_kernel(const float* __restrict__ E) {
    __shared__ unsigned As[32][72];   // padded: (8*tig+gid) bank-conflict-free
    __shared__ unsigned Bs[32][72];

    const int tid   = threadIdx.x;
    const int pair  = blockIdx.x / NKCH;
    const int chunk = blockIdx.x % NKCH;
    const int i0 = c_ti[pair] * 64;
    const int j0 = c_tj[pair] * 64;
    const int k0 = chunk * KCHUNK;
    const bool diag = (i0 == j0);

    const int w    = tid >> 5;
    const int lane = tid & 31;
    const int gid  = lane >> 2;       // 0..7
    const int tig  = lane & 3;        // 0..3
    const int iw   = (w >> 1) * 16;   // 4 m-bands
    const int jw   = (w & 1) * 32;    // 2 n-bands

    float acc[4][4];
    #pragma unroll
    for (int t = 0; t < 4; ++t)
        #pragma unroll
        for (int c = 0; c < 4; ++c) acc[t][c] = 0.0f;

    for (int kc = 0; kc < KCHUNK; kc += 32) {
        // Stage 32 rows x 64 cols (converted to tf32). 8 floats per thread/array.
        #pragma unroll
        for (int q = 0; q < 2; ++q) {
            int slot = q * 256 + tid;          // 0..511
            int row  = slot >> 4;
            int f    = slot & 15;
            size_t base = (size_t)(k0 + kc + row) * W;
            float4 va = ((const float4*)(E + base + i0))[f];
            uint4 ua = make_uint4(f2tf32(va.x), f2tf32(va.y), f2tf32(va.z), f2tf32(va.w));
            *(uint4*)&As[row][f * 4] = ua;
            if (!diag) {
                float4 vb = ((const float4*)(E + base + j0))[f];
                uint4 ub = make_uint4(f2tf32(vb.x), f2tf32(vb.y), f2tf32(vb.z), f2tf32(vb.w));
                *(uint4*)&Bs[row][f * 4] = ub;
            }
        }
        __syncthreads();

        const unsigned (*Bp)[72] = diag ? As : Bs;

        #pragma unroll
        for (int kb = 0; kb < 32; kb += 8) {
            unsigned a[4];
            a[0] = As[kb + tig    ][iw + gid    ];
            a[1] = As[kb + tig    ][iw + gid + 8];
            a[2] = As[kb + tig + 4][iw + gid    ];
            a[3] = As[kb + tig + 4][iw + gid + 8];
            #pragma unroll
            for (int t = 0; t < 4; ++t) {
                unsigned b[2];
                b[0] = Bp[kb + tig    ][jw + t * 8 + gid];
                b[1] = Bp[kb + tig + 4][jw + t * 8 + gid];
                mma_tf32(acc[t], a, b);
            }
        }
        __syncthreads();
    }

    // Store partial tile (no atomics; finalize sums the chunks).
    float* out = g_Gs[chunk];
    const int gi = i0 + iw + gid;
    #pragma unroll
    for (int t = 0; t < 4; ++t) {
        int gj = j0 + jw + t * 8 + 2 * tig;
        *(float2*)&out[gi * W + gj]       = make_float2(acc[t][0], acc[t][1]);
        *(float2*)&out[(gi + 8) * W + gj] = make_float2(acc[t][2], acc[t][3]);
    }
}

// ---------------------------------------------------------------------------
// K3: finalize. 128 blocks x 256 threads; block b -> rows b and 255-b (upper
// triangle). Diagonal uses exact fp32 sumsq. Last block writes sqrt and
// resets the self-resetting accumulators for the next graph replay.
// ---------------------------------------------------------------------------
__global__ void finalize_kernel(float* __restrict__ out) {
    __shared__ float mu[W];
    __shared__ float sq[W];
    __shared__ float red[256];
    __shared__ int   is_last;

    const int t = threadIdx.x;
    const float invB = 1.0f / BATCH;
    mu[t] = g_musum[t] * invB;
    sq[t] = g_sqsum[t];
    __syncthreads();

    float acc = 0.0f;
    int rows[2] = {(int)blockIdx.x, (W - 1) - (int)blockIdx.x};
    #pragma unroll
    for (int r = 0; r < 2; ++r) {
        int i = rows[r];
        int j = i + t;                 // upper triangle only
        if (j < W) {
            float d;
            if (t == 0) {
                d = sq[i] * invB - mu[i] * mu[i] - 1.0f;   // exact diagonal
                acc += d * d;
            } else {
                float G = 0.0f;
                #pragma unroll
                for (int s = 0; s < NKCH; ++s) G += g_Gs[s][i * W + j];
                d = G * invB - mu[i] * mu[j];
                acc += 2.0f * d * d;
            }
        }
    }

    red[t] = acc;
    __syncthreads();
    #pragma unroll
    for (int st = 128; st > 0; st >>= 1) {
        if (t < st) red[t] += red[t + st];
        __syncthreads();
    }

    if (t == 0) {
        atomicAdd(&g_sumsq, red[0]);
        __threadfence();
        int c = atomicAdd(&g_fin_count, 1);
        is_last = (c == (W / 2 - 1));
    }
    __syncthreads();
    if (is_last) {
        // All 128 blocks have accumulated; safe to emit and reset.
        g_musum[t] = 0.0f;
        g_sqsum[t] = 0.0f;
        if (t == 0) {
            float total = atomicAdd(&g_sumsq, 0.0f);   // coherent read
            out[0] = sqrtf(total);
            g_fin_count = 0;
        }
    }
}

// ---------------------------------------------------------------------------
extern "C" void kernel_launch(void* const* d_in, const int* in_sizes, int n_in,
                              void* d_out, int out_size) {
    const float* E = (const float*)d_in[0];   // [8192, 256] fp32
    float* out = (float*)d_out;

    colsum_kernel<<<NCSB, 256>>>(E);
    gram_kernel<<<NPAIR * NKCH, 256>>>(E);
    finalize_kernel<<<W / 2, 256>>>(out);
}

// round 14
// speedup vs baseline: 1.8668x; 1.2637x over previous
#include <cuda_runtime.h>
#include <math.h>

#define BATCH 8192
#define W 256
#define NKCH 64
#define KCHUNK (BATCH / NKCH)        // 128
#define NPAIR 3                      // 128x128 tile-pairs: (0,0),(0,1),(1,1)

// Device scratch (no allocations allowed). All self-resetting across replays.
__device__ float g_G[W * W];          // Gram accumulator (zeroed by finalize)
__device__ float g_musum[W] = {};     // column sums
__device__ float g_sqsum[W] = {};     // column sum-of-squares (exact diagonal)
__device__ float g_sumsq;             // ||D||^2 accumulator
__device__ int   g_fin_count = 0;     // finalize completion counter

// ---- helpers ---------------------------------------------------------------
__device__ __forceinline__ unsigned f2tf32(float x) {
    unsigned r;
    asm("cvt.rna.tf32.f32 %0, %1;" : "=r"(r) : "f"(x));
    return r;
}
__device__ __forceinline__ void mma_tf32(float* d, const unsigned* a, const unsigned* b) {
    asm("mma.sync.aligned.m16n8k8.row.col.f32.tf32.tf32.f32 "
        "{%0,%1,%2,%3}, {%4,%5,%6,%7}, {%8,%9}, {%0,%1,%2,%3};"
        : "+f"(d[0]), "+f"(d[1]), "+f"(d[2]), "+f"(d[3])
        : "r"(a[0]), "r"(a[1]), "r"(a[2]), "r"(a[3]), "r"(b[0]), "r"(b[1]));
}

// ---------------------------------------------------------------------------
// K1: Gram via TF32 MMA on 128x128 symmetric tile-pairs + fused column stats.
// Grid 192 = 3 pairs x 64 K-chunks; 256 threads = 8 warps, warp tile 32x64.
// Diagonal-pair blocks also accumulate column sum / sum-of-squares (fp32 exact)
// from the staged data: pairs (0,0) and (1,1) jointly cover every (col, row)
// of E exactly once.
// ---------------------------------------------------------------------------
__global__ __launch_bounds__(256) void gram_kernel(const float* __restrict__ E) {
    __shared__ unsigned As[32][136];   // pad 136: 136%32==8 -> (8*tig+gid) conflict-free
    __shared__ unsigned Bs[32][136];
    __shared__ float s_sum[128];
    __shared__ float s_sq[128];

    const int tid   = threadIdx.x;
    const int pair  = blockIdx.x / NKCH;         // 0:(0,0) 1:(0,1) 2:(1,1)
    const int chunk = blockIdx.x % NKCH;
    const int i0 = (pair == 2) ? 128 : 0;
    const int j0 = (pair == 0) ? 0 : 128;
    const int k0 = chunk * KCHUNK;
    const bool diag = (i0 == j0);

    const int w    = tid >> 5;
    const int lane = tid & 31;
    const int gid  = lane >> 2;       // 0..7
    const int tig  = lane & 3;        // 0..3
    const int iw   = (w >> 1) * 32;   // 4 m-bands of 32
    const int jw   = (w & 1) * 64;    // 2 n-bands of 64

    float acc[2][8][4];
    #pragma unroll
    for (int m = 0; m < 2; ++m)
        #pragma unroll
        for (int n = 0; n < 8; ++n)
            #pragma unroll
            for (int c = 0; c < 4; ++c) acc[m][n][c] = 0.0f;

    // Column-stat accumulators (diag blocks): thread owns cols f*4..f*4+3.
    float4 csum = make_float4(0.f, 0.f, 0.f, 0.f);
    float4 csq  = make_float4(0.f, 0.f, 0.f, 0.f);
    if (tid < 128) { s_sum[tid] = 0.0f; s_sq[tid] = 0.0f; }

    const int f  = tid & 31;          // float4 index within 128-col row
    const int r0 = tid >> 5;          // base row (0..7)

    for (int kc = 0; kc < KCHUNK; kc += 32) {
        // Stage 32 rows x 128 cols (tf32-converted); 4 float4 per thread/array.
        #pragma unroll
        for (int q = 0; q < 4; ++q) {
            int row = q * 8 + r0;
            size_t base = (size_t)(k0 + kc + row) * W;
            float4 va = ((const float4*)(E + base + i0))[f];
            *(uint4*)&As[row][f * 4] =
                make_uint4(f2tf32(va.x), f2tf32(va.y), f2tf32(va.z), f2tf32(va.w));
            if (diag) {
                csum.x += va.x; csq.x = fmaf(va.x, va.x, csq.x);
                csum.y += va.y; csq.y = fmaf(va.y, va.y, csq.y);
                csum.z += va.z; csq.z = fmaf(va.z, va.z, csq.z);
                csum.w += va.w; csq.w = fmaf(va.w, va.w, csq.w);
            } else {
                float4 vb = ((const float4*)(E + base + j0))[f];
                *(uint4*)&Bs[row][f * 4] =
                    make_uint4(f2tf32(vb.x), f2tf32(vb.y), f2tf32(vb.z), f2tf32(vb.w));
            }
        }
        __syncthreads();

        const unsigned (*Bp)[136] = diag ? As : Bs;

        #pragma unroll
        for (int kb = 0; kb < 32; kb += 8) {
            unsigned a[2][4];
            #pragma unroll
            for (int m = 0; m < 2; ++m) {
                int mi = iw + m * 16;
                a[m][0] = As[kb + tig    ][mi + gid    ];
                a[m][1] = As[kb + tig    ][mi + gid + 8];
                a[m][2] = As[kb + tig + 4][mi + gid    ];
                a[m][3] = As[kb + tig + 4][mi + gid + 8];
            }
            #pragma unroll
            for (int n = 0; n < 8; ++n) {
                unsigned b[2];
                b[0] = Bp[kb + tig    ][jw + n * 8 + gid];
                b[1] = Bp[kb + tig + 4][jw + n * 8 + gid];
                mma_tf32(acc[0][n], a[0], b);
                mma_tf32(acc[1][n], a[1], b);
            }
        }
        __syncthreads();
    }

    // Accumulate the tile into g_G (finalize zeroes it after reading).
    #pragma unroll
    for (int m = 0; m < 2; ++m) {
        int gi = i0 + iw + m * 16 + gid;
        #pragma unroll
        for (int n = 0; n < 8; ++n) {
            int gj = j0 + jw + n * 8 + 2 * tig;
            atomicAdd(&g_G[gi * W + gj],           acc[m][n][0]);
            atomicAdd(&g_G[gi * W + gj + 1],       acc[m][n][1]);
            atomicAdd(&g_G[(gi + 8) * W + gj],     acc[m][n][2]);
            atomicAdd(&g_G[(gi + 8) * W + gj + 1], acc[m][n][3]);
        }
    }

    // Diagonal blocks: reduce column stats (8 threads share each f).
    if (diag) {
        atomicAdd(&s_sum[f * 4 + 0], csum.x);
        atomicAdd(&s_sum[f * 4 + 1], csum.y);
        atomicAdd(&s_sum[f * 4 + 2], csum.z);
        atomicAdd(&s_sum[f * 4 + 3], csum.w);
        atomicAdd(&s_sq[f * 4 + 0], csq.x);
        atomicAdd(&s_sq[f * 4 + 1], csq.y);
        atomicAdd(&s_sq[f * 4 + 2], csq.z);
        atomicAdd(&s_sq[f * 4 + 3], csq.w);
        __syncthreads();
        if (tid < 128) {
            atomicAdd(&g_musum[i0 + tid], s_sum[tid]);
            atomicAdd(&g_sqsum[i0 + tid], s_sq[tid]);
        }
    }
}

// ---------------------------------------------------------------------------
// K2: finalize. 128 blocks x 256 threads; block b -> rows b and 255-b (upper
// triangle). Diagonal uses exact fp32 sumsq. Each block zeroes the g_G rows it
// owns (replay-safe). Last block writes sqrt and resets all accumulators.
// ---------------------------------------------------------------------------
__global__ void finalize_kernel(float* __restrict__ out) {
    __shared__ float mu[W];
    __shared__ float sq[W];
    __shared__ float red[256];
    __shared__ int   is_last;

    const int t = threadIdx.x;
    const float invB = 1.0f / BATCH;
    mu[t] = g_musum[t] * invB;
    sq[t] = g_sqsum[t];
    __syncthreads();

    float acc = 0.0f;
    int rows[2] = {(int)blockIdx.x, (W - 1) - (int)blockIdx.x};
    #pragma unroll
    for (int r = 0; r < 2; ++r) {
        int i = rows[r];
        int j = i + t;                 // upper triangle only
        if (j < W) {
            if (t == 0) {
                float d = sq[i] * invB - mu[i] * mu[i] - 1.0f;  // exact diagonal
                acc += d * d;
            } else {
                float d = g_G[i * W + j] * invB - mu[i] * mu[j];
                acc += 2.0f * d * d;
            }
        }
    }

    __syncthreads();                   // all reads of owned rows complete
    g_G[rows[0] * W + t] = 0.0f;       // zero owned rows for next replay
    g_G[rows[1] * W + t] = 0.0f;

    red[t] = acc;
    __syncthreads();
    #pragma unroll
    for (int st = 128; st > 0; st >>= 1) {
        if (t < st) red[t] += red[t + st];
        __syncthreads();
    }

    if (t == 0) {
        atomicAdd(&g_sumsq, red[0]);
        __threadfence();
        int c = atomicAdd(&g_fin_count, 1);
        is_last = (c == (W / 2 - 1));
    }
    __syncthreads();
    if (is_last) {
        g_musum[t] = 0.0f;             // reset column stats for next replay
        g_sqsum[t] = 0.0f;
        if (t == 0) {
            float total = atomicAdd(&g_sumsq, 0.0f);   // coherent read
            out[0] = sqrtf(total);
            g_sumsq = 0.0f;
            g_fin_count = 0;
        }
    }
}

// ---------------------------------------------------------------------------
extern "C" void kernel_launch(void* const* d_in, const int* in_sizes, int n_in,
                              void* d_out, int out_size) {
    const float* E = (const float*)d_in[0];   // [8192, 256] fp32
    float* out = (float*)d_out;

    gram_kernel<<<NPAIR * NKCH, 256>>>(E);
    finalize_kernel<<<W / 2, 256>>>(out);
}